// round 1
// baseline (speedup 1.0000x reference)
#include <cuda_runtime.h>
#include <cstdint>

#define N_PTS    8192
#define N_SMP    2048
#define BATCH    8
#define CHANNELS 128

// ---------------------------------------------------------------------------
// Kernel 1: farthest point sampling. One block (1024 threads) per batch.
// Each thread owns 8 points (idx = t + 1024*s) in registers; the whole cloud
// is mirrored in dynamic SMEM so any thread can read the current centroid.
// Writes sampled_pos (8,3,2048) directly into its region of d_out.
// ---------------------------------------------------------------------------
__global__ void __launch_bounds__(1024, 1)
fps_kernel(const float* __restrict__ pos, float* __restrict__ sampled)
{
    extern __shared__ float smem[];
    float* xs = smem;                 // [8192]
    float* ys = smem + N_PTS;         // [8192]
    float* zs = smem + 2 * N_PTS;     // [8192]
    __shared__ float s_vals[32];
    __shared__ int   s_idxs[32];
    __shared__ int   s_far;

    const int b = blockIdx.x;
    const int t = threadIdx.x;
    const int lane = t & 31;
    const int warp = t >> 5;
    const float* p = pos + (size_t)b * 3 * N_PTS;

    float x[8], y[8], z[8], dist[8];
#pragma unroll
    for (int s = 0; s < 8; s++) {
        int j = t + (s << 10);
        x[s] = p[j];
        y[s] = p[N_PTS + j];
        z[s] = p[2 * N_PTS + j];
        xs[j] = x[s];
        ys[j] = y[s];
        zs[j] = z[s];
        dist[s] = 1e10f;   // matches reference init 10000000000.0
    }
    __syncthreads();

    int far = 0;
    float* out = sampled + (size_t)b * 3 * N_SMP;

    for (int m = 0; m < N_SMP; m++) {
        // centroid = pos[:, far]; broadcast LDS (conflict-free)
        float cx = xs[far], cy = ys[far], cz = zs[far];
        if (t == 0) {
            // scan emits `farthest` at step entry -> sampled_pos[m] uses it
            out[m]             = cx;
            out[N_SMP + m]     = cy;
            out[2 * N_SMP + m] = cz;
        }

        // update min-dist + local argmax (ascending idx order -> ties keep
        // earliest, matching jnp.argmax first-occurrence semantics)
        float best = -1.0f;
        int   bidx = 0;
#pragma unroll
        for (int s = 0; s < 8; s++) {
            float dx = x[s] - cx;
            float dy = y[s] - cy;
            float dz = z[s] - cz;
            // no FMA contraction: square then ((xx+yy)+zz), like XLA's
            // elementwise-square + axis-0 reduce
            float d = __fadd_rn(__fadd_rn(__fmul_rn(dx, dx), __fmul_rn(dy, dy)),
                                __fmul_rn(dz, dz));
            float nd = fminf(dist[s], d);
            dist[s] = nd;
            if (nd > best) { best = nd; bidx = t + (s << 10); }
        }

        // warp argmax, lexicographic (val desc, idx asc on ties)
#pragma unroll
        for (int off = 16; off > 0; off >>= 1) {
            float ov = __shfl_down_sync(0xffffffffu, best, off);
            int   oi = __shfl_down_sync(0xffffffffu, bidx, off);
            if (ov > best || (ov == best && oi < bidx)) { best = ov; bidx = oi; }
        }
        if (lane == 0) { s_vals[warp] = best; s_idxs[warp] = bidx; }
        __syncthreads();

        if (warp == 0) {
            best = s_vals[lane];
            bidx = s_idxs[lane];
#pragma unroll
            for (int off = 16; off > 0; off >>= 1) {
                float ov = __shfl_down_sync(0xffffffffu, best, off);
                int   oi = __shfl_down_sync(0xffffffffu, bidx, off);
                if (ov > best || (ov == best && oi < bidx)) { best = ov; bidx = oi; }
            }
            if (lane == 0) s_far = bidx;
        }
        __syncthreads();
        far = s_far;
    }
}

// ---------------------------------------------------------------------------
// Kernel 2: 4-NN search + channel max-pool. One thread per query point.
// grid (16, 8), 128 threads: block loads the whole cloud (pos + precomputed
// p2, 128 KB as float4) into SMEM; every thread scans all 8192 candidates
// (broadcast LDS.128), keeping a sorted top-4. Then gathers 4 feature
// columns per channel and max-reduces.
// ---------------------------------------------------------------------------
__global__ void __launch_bounds__(128, 1)
knn_pool_kernel(const float* __restrict__ feats,
                const float* __restrict__ pos,
                const float* __restrict__ sampled,
                float* __restrict__ pooled)
{
    extern __shared__ float4 tile[];   // [8192] = 128 KB: (x, y, z, p2)

    const int b = blockIdx.y;
    const int t = threadIdx.x;
    const int q = blockIdx.x * blockDim.x + t;   // query 0..2047

    const float* p = pos + (size_t)b * 3 * N_PTS;
    for (int j = t; j < N_PTS; j += blockDim.x) {
        float px = p[j];
        float py = p[N_PTS + j];
        float pz = p[2 * N_PTS + j];
        float p2 = __fadd_rn(__fadd_rn(__fmul_rn(px, px), __fmul_rn(py, py)),
                             __fmul_rn(pz, pz));
        tile[j] = make_float4(px, py, pz, p2);
    }
    __syncthreads();

    const float* sp = sampled + (size_t)b * 3 * N_SMP;
    float sx = sp[q];
    float sy = sp[N_SMP + q];
    float sz = sp[2 * N_SMP + q];
    float s2 = __fadd_rn(__fadd_rn(__fmul_rn(sx, sx), __fmul_rn(sy, sy)),
                         __fmul_rn(sz, sz));

    const float INF = __int_as_float(0x7f800000);
    float d0 = INF, d1 = INF, d2 = INF, d3 = INF;
    int   i0 = 0,   i1 = 0,   i2 = 0,   i3 = 0;

    // ascending scan: strict '<' insertion reproduces top_k's stable
    // (first-index-on-tie) selection of the 4 smallest distances
#pragma unroll 4
    for (int j = 0; j < N_PTS; j++) {
        float4 pt = tile[j];
        float cross = __fadd_rn(__fadd_rn(__fmul_rn(sx, pt.x), __fmul_rn(sy, pt.y)),
                                __fmul_rn(sz, pt.z));
        // dist = (s2 + p2) - 2*cross, same association as the reference
        float dv = __fsub_rn(__fadd_rn(s2, pt.w), __fmul_rn(2.0f, cross));
        if (dv < d3) {
            if (dv < d2) {
                d3 = d2; i3 = i2;
                if (dv < d1) {
                    d2 = d1; i2 = i1;
                    if (dv < d0) { d1 = d0; i1 = i0; d0 = dv; i0 = j; }
                    else         { d1 = dv; i1 = j; }
                } else { d2 = dv; i2 = j; }
            } else { d3 = dv; i3 = j; }
        }
    }

    // channel-wise max over the 4 neighbor feature columns
    const float* f0 = feats + (size_t)b * CHANNELS * N_PTS;
    float* outp = pooled + (size_t)b * CHANNELS * N_SMP + q;
#pragma unroll 4
    for (int c = 0; c < CHANNELS; c++) {
        const float* fc = f0 + (size_t)c * N_PTS;
        float v = fmaxf(fmaxf(__ldg(fc + i0), __ldg(fc + i1)),
                        fmaxf(__ldg(fc + i2), __ldg(fc + i3)));
        outp[(size_t)c * N_SMP] = v;
    }
}

// ---------------------------------------------------------------------------
// Launch
// ---------------------------------------------------------------------------
extern "C" void kernel_launch(void* const* d_in, const int* in_sizes, int n_in,
                              void* d_out, int out_size)
{
    const float* feats = (const float*)d_in[0];   // (8,128,8192)
    const float* pos   = (const float*)d_in[1];   // (8,3,8192)

    float* pooled  = (float*)d_out;                                   // (8,128,2048)
    float* sampled = (float*)d_out + (size_t)BATCH * CHANNELS * N_SMP; // (8,3,2048)

    const int fps_smem = 3 * N_PTS * (int)sizeof(float);      // 96 KB
    const int knn_smem = N_PTS * (int)sizeof(float4);         // 128 KB
    cudaFuncSetAttribute(fps_kernel,
                         cudaFuncAttributeMaxDynamicSharedMemorySize, fps_smem);
    cudaFuncSetAttribute(knn_pool_kernel,
                         cudaFuncAttributeMaxDynamicSharedMemorySize, knn_smem);

    fps_kernel<<<BATCH, 1024, fps_smem>>>(pos, sampled);

    dim3 grid(N_SMP / 128, BATCH);
    knn_pool_kernel<<<grid, 128, knn_smem>>>(feats, pos, sampled, pooled);
}

// round 3
// speedup vs baseline: 1.5617x; 1.5617x over previous
#include <cuda_runtime.h>
#include <cstdint>

#define N_PTS    8192
#define N_SMP    2048
#define BATCH    8
#define CHANNELS 128

// ---- packed f32x2 helpers (two independent rn-rounded f32 ops per instr).
// Fallback path is two scalar rn ops: bit-identical results either way. ----
#if defined(__CUDA_ARCH__) && (__CUDA_ARCH__ >= 1000)
#define HAS_F32X2 1
#else
#define HAS_F32X2 0
#endif

struct P2 { float lo, hi; };

__device__ __forceinline__ P2 pk2(float a, float b) { P2 r; r.lo = a; r.hi = b; return r; }

__device__ __forceinline__ P2 add2(P2 a, P2 b) {
#if HAS_F32X2
    unsigned long long av, bv, rv;
    asm("mov.b64 %0, {%1, %2};" : "=l"(av) : "f"(a.lo), "f"(a.hi));
    asm("mov.b64 %0, {%1, %2};" : "=l"(bv) : "f"(b.lo), "f"(b.hi));
    asm("add.rn.f32x2 %0, %1, %2;" : "=l"(rv) : "l"(av), "l"(bv));
    P2 r;
    asm("mov.b64 {%0, %1}, %2;" : "=f"(r.lo), "=f"(r.hi) : "l"(rv));
    return r;
#else
    P2 r; r.lo = __fadd_rn(a.lo, b.lo); r.hi = __fadd_rn(a.hi, b.hi); return r;
#endif
}

__device__ __forceinline__ P2 mul2(P2 a, P2 b) {
#if HAS_F32X2
    unsigned long long av, bv, rv;
    asm("mov.b64 %0, {%1, %2};" : "=l"(av) : "f"(a.lo), "f"(a.hi));
    asm("mov.b64 %0, {%1, %2};" : "=l"(bv) : "f"(b.lo), "f"(b.hi));
    asm("mul.rn.f32x2 %0, %1, %2;" : "=l"(rv) : "l"(av), "l"(bv));
    P2 r;
    asm("mov.b64 {%0, %1}, %2;" : "=f"(r.lo), "=f"(r.hi) : "l"(rv));
    return r;
#else
    P2 r; r.lo = __fmul_rn(a.lo, b.lo); r.hi = __fmul_rn(a.hi, b.hi); return r;
#endif
}

// ---------------------------------------------------------------------------
// Kernel 1: farthest point sampling. One block (1024 threads) per batch.
// 8 points/thread in packed f32x2 registers; cloud mirrored in SMEM for
// centroid broadcast. Per iteration: packed distance update, REDUX warp
// argmax, ONE barrier, then every warp redundantly REDUX-reduces the 32
// double-buffered warp candidates (no broadcast barrier needed).
// ---------------------------------------------------------------------------
__global__ void __launch_bounds__(1024, 1)
fps_kernel(const float* __restrict__ pos, float* __restrict__ sampled)
{
    extern __shared__ float smem[];
    float* xs = smem;                 // [8192]
    float* ys = smem + N_PTS;         // [8192]
    float* zs = smem + 2 * N_PTS;     // [8192]
    __shared__ unsigned s_val[2][32];
    __shared__ unsigned s_idx[2][32];

    const int b = blockIdx.x;
    const int t = threadIdx.x;
    const int lane = t & 31;
    const int warp = t >> 5;
    const float* p = pos + (size_t)b * 3 * N_PTS;

    // slot s owns point j = t + s*1024; pair q packs slots (2q, 2q+1)
    P2 x2[4], y2[4], z2[4];
    float dist[8];
    {
        float xv[8], yv[8], zv[8];
#pragma unroll
        for (int s = 0; s < 8; s++) {
            int j = t + (s << 10);
            xv[s] = p[j];
            yv[s] = p[N_PTS + j];
            zv[s] = p[2 * N_PTS + j];
            xs[j] = xv[s];
            ys[j] = yv[s];
            zs[j] = zv[s];
            dist[s] = 1e10f;   // reference init 10000000000.0
        }
#pragma unroll
        for (int q = 0; q < 4; q++) {
            x2[q] = pk2(xv[2 * q], xv[2 * q + 1]);
            y2[q] = pk2(yv[2 * q], yv[2 * q + 1]);
            z2[q] = pk2(zv[2 * q], zv[2 * q + 1]);
        }
    }
    __syncthreads();

    int far = 0;
    int buf = 0;
    float* out = sampled + (size_t)b * 3 * N_SMP;

    for (int m = 0; m < N_SMP; m++) {
        float cx = xs[far], cy = ys[far], cz = zs[far];
        if (t == 0) {
            // scan emits `farthest` at step entry
            out[m]             = cx;
            out[N_SMP + m]     = cy;
            out[2 * N_SMP + m] = cz;
        }
        P2 ncx = pk2(-cx, -cx);
        P2 ncy = pk2(-cy, -cy);
        P2 ncz = pk2(-cz, -cz);

        // per-thread argmax: dist >= 0 so float bits order as u32.
        // strict '>' with ascending j keeps first occurrence.
        unsigned bestb = 0u;
        int bidx = t;            // smallest index this thread owns
#pragma unroll
        for (int q = 0; q < 4; q++) {
            P2 dx = add2(x2[q], ncx);   // x - cx (exact: add of negation)
            P2 dy = add2(y2[q], ncy);
            P2 dz = add2(z2[q], ncz);
            P2 xx = mul2(dx, dx);
            P2 yy = mul2(dy, dy);
            P2 zz = mul2(dz, dz);
            P2 d2 = add2(add2(xx, yy), zz);   // ((xx+yy)+zz), each rn
            float nlo = fminf(dist[2 * q], d2.lo);
            float nhi = fminf(dist[2 * q + 1], d2.hi);
            dist[2 * q]     = nlo;
            dist[2 * q + 1] = nhi;
            unsigned blo = __float_as_uint(nlo);
            if (blo > bestb) { bestb = blo; bidx = t + (q << 11); }
            unsigned bhi = __float_as_uint(nhi);
            if (bhi > bestb) { bestb = bhi; bidx = t + (q << 11) + 1024; }
        }

        // warp argmax via REDUX: max value bits, then min index among matches
        unsigned wmax = __reduce_max_sync(0xffffffffu, bestb);
        unsigned cand = (bestb == wmax) ? (unsigned)bidx : 0xffffffffu;
        unsigned widx = __reduce_min_sync(0xffffffffu, cand);
        if (lane == 0) { s_val[buf][warp] = wmax; s_idx[buf][warp] = widx; }
        __syncthreads();

        // every warp reduces the 32 candidates (double-buffered, race-free)
        unsigned v = s_val[buf][lane];
        unsigned i = s_idx[buf][lane];
        unsigned gmax = __reduce_max_sync(0xffffffffu, v);
        unsigned gc   = (v == gmax) ? i : 0xffffffffu;
        far = (int)__reduce_min_sync(0xffffffffu, gc);
        buf ^= 1;
    }
}

// ---------------------------------------------------------------------------
// Kernel 2: 4-NN search + channel max-pool. 256 threads/block, one thread
// per query. Block caches cloud (pos + p2) as float4 in SMEM; each thread
// scans 8192 candidates keeping a sorted top-4, then max-pools 4 feature
// columns per channel.
// ---------------------------------------------------------------------------
__global__ void __launch_bounds__(256, 1)
knn_pool_kernel(const float* __restrict__ feats,
                const float* __restrict__ pos,
                const float* __restrict__ sampled,
                float* __restrict__ pooled)
{
    extern __shared__ float4 tile[];   // [8192] = 128 KB: (x, y, z, p2)

    const int b = blockIdx.y;
    const int t = threadIdx.x;
    const int q = blockIdx.x * blockDim.x + t;

    const float* p = pos + (size_t)b * 3 * N_PTS;
    for (int j = t; j < N_PTS; j += blockDim.x) {
        float px = p[j];
        float py = p[N_PTS + j];
        float pz = p[2 * N_PTS + j];
        float p2 = __fadd_rn(__fadd_rn(__fmul_rn(px, px), __fmul_rn(py, py)),
                             __fmul_rn(pz, pz));
        tile[j] = make_float4(px, py, pz, p2);
    }
    __syncthreads();

    const float* sp = sampled + (size_t)b * 3 * N_SMP;
    float sx = sp[q];
    float sy = sp[N_SMP + q];
    float sz = sp[2 * N_SMP + q];
    float s2 = __fadd_rn(__fadd_rn(__fmul_rn(sx, sx), __fmul_rn(sy, sy)),
                         __fmul_rn(sz, sz));

    const float INF = __int_as_float(0x7f800000);
    float d0 = INF, d1 = INF, d2 = INF, d3 = INF;
    int   i0 = 0,   i1 = 0,   i2 = 0,   i3 = 0;

#pragma unroll 8
    for (int j = 0; j < N_PTS; j++) {
        float4 pt = tile[j];
        float cross = __fadd_rn(__fadd_rn(__fmul_rn(sx, pt.x), __fmul_rn(sy, pt.y)),
                                __fmul_rn(sz, pt.z));
        float dv = __fsub_rn(__fadd_rn(s2, pt.w), __fmul_rn(2.0f, cross));
        if (dv < d3) {
            if (dv < d2) {
                d3 = d2; i3 = i2;
                if (dv < d1) {
                    d2 = d1; i2 = i1;
                    if (dv < d0) { d1 = d0; i1 = i0; d0 = dv; i0 = j; }
                    else         { d1 = dv; i1 = j; }
                } else { d2 = dv; i2 = j; }
            } else { d3 = dv; i3 = j; }
        }
    }

    const float* f0 = feats + (size_t)b * CHANNELS * N_PTS;
    float* outp = pooled + (size_t)b * CHANNELS * N_SMP + q;
#pragma unroll 4
    for (int c = 0; c < CHANNELS; c++) {
        const float* fc = f0 + (size_t)c * N_PTS;
        float v = fmaxf(fmaxf(__ldg(fc + i0), __ldg(fc + i1)),
                        fmaxf(__ldg(fc + i2), __ldg(fc + i3)));
        outp[(size_t)c * N_SMP] = v;
    }
}

// ---------------------------------------------------------------------------
// Launch
// ---------------------------------------------------------------------------
extern "C" void kernel_launch(void* const* d_in, const int* in_sizes, int n_in,
                              void* d_out, int out_size)
{
    const float* feats = (const float*)d_in[0];   // (8,128,8192)
    const float* pos   = (const float*)d_in[1];   // (8,3,8192)

    float* pooled  = (float*)d_out;                                    // (8,128,2048)
    float* sampled = (float*)d_out + (size_t)BATCH * CHANNELS * N_SMP; // (8,3,2048)

    const int fps_smem = 3 * N_PTS * (int)sizeof(float);      // 96 KB
    const int knn_smem = N_PTS * (int)sizeof(float4);         // 128 KB
    cudaFuncSetAttribute(fps_kernel,
                         cudaFuncAttributeMaxDynamicSharedMemorySize, fps_smem);
    cudaFuncSetAttribute(knn_pool_kernel,
                         cudaFuncAttributeMaxDynamicSharedMemorySize, knn_smem);

    fps_kernel<<<BATCH, 1024, fps_smem>>>(pos, sampled);

    dim3 grid(N_SMP / 256, BATCH);
    knn_pool_kernel<<<grid, 256, knn_smem>>>(feats, pos, sampled, pooled);
}

// round 5
// speedup vs baseline: 1.8013x; 1.1535x over previous
#include <cuda_runtime.h>
#include <cstdint>

#define N_PTS    8192
#define N_SMP    2048
#define BATCH    8
#define CHANNELS 128

// ---- packed f32x2 helpers (two independent rn-rounded f32 ops per instr).
// Fallback path is two scalar rn ops: bit-identical results either way. ----
#if defined(__CUDA_ARCH__) && (__CUDA_ARCH__ >= 1000)
#define HAS_F32X2 1
#else
#define HAS_F32X2 0
#endif

struct P2 { float lo, hi; };

__device__ __forceinline__ P2 pk2(float a, float b) { P2 r; r.lo = a; r.hi = b; return r; }

__device__ __forceinline__ P2 add2(P2 a, P2 b) {
#if HAS_F32X2
    unsigned long long av, bv, rv;
    asm("mov.b64 %0, {%1, %2};" : "=l"(av) : "f"(a.lo), "f"(a.hi));
    asm("mov.b64 %0, {%1, %2};" : "=l"(bv) : "f"(b.lo), "f"(b.hi));
    asm("add.rn.f32x2 %0, %1, %2;" : "=l"(rv) : "l"(av), "l"(bv));
    P2 r;
    asm("mov.b64 {%0, %1}, %2;" : "=f"(r.lo), "=f"(r.hi) : "l"(rv));
    return r;
#else
    P2 r; r.lo = __fadd_rn(a.lo, b.lo); r.hi = __fadd_rn(a.hi, b.hi); return r;
#endif
}

__device__ __forceinline__ P2 mul2(P2 a, P2 b) {
#if HAS_F32X2
    unsigned long long av, bv, rv;
    asm("mov.b64 %0, {%1, %2};" : "=l"(av) : "f"(a.lo), "f"(a.hi));
    asm("mov.b64 %0, {%1, %2};" : "=l"(bv) : "f"(b.lo), "f"(b.hi));
    asm("mul.rn.f32x2 %0, %1, %2;" : "=l"(rv) : "l"(av), "l"(bv));
    P2 r;
    asm("mov.b64 {%0, %1}, %2;" : "=f"(r.lo), "=f"(r.hi) : "l"(rv));
    return r;
#else
    P2 r; r.lo = __fmul_rn(a.lo, b.lo); r.hi = __fmul_rn(a.hi, b.hi); return r;
#endif
}

// ---------------------------------------------------------------------------
// Kernel 1: farthest point sampling. One block (1024 threads) per batch.
// 8 points/thread in packed f32x2 registers; cloud mirrored in SMEM for
// centroid broadcast. Per iteration: packed distance update, REDUX warp
// argmax, ONE barrier, then every warp redundantly REDUX-reduces the 32
// double-buffered warp candidates (no broadcast barrier needed).
// (unchanged from the passing rel_err=0.0 version)
// ---------------------------------------------------------------------------
__global__ void __launch_bounds__(1024, 1)
fps_kernel(const float* __restrict__ pos, float* __restrict__ sampled)
{
    extern __shared__ float smem[];
    float* xs = smem;                 // [8192]
    float* ys = smem + N_PTS;         // [8192]
    float* zs = smem + 2 * N_PTS;     // [8192]
    __shared__ unsigned s_val[2][32];
    __shared__ unsigned s_idx[2][32];

    const int b = blockIdx.x;
    const int t = threadIdx.x;
    const int lane = t & 31;
    const int warp = t >> 5;
    const float* p = pos + (size_t)b * 3 * N_PTS;

    P2 x2[4], y2[4], z2[4];
    float dist[8];
    {
        float xv[8], yv[8], zv[8];
#pragma unroll
        for (int s = 0; s < 8; s++) {
            int j = t + (s << 10);
            xv[s] = p[j];
            yv[s] = p[N_PTS + j];
            zv[s] = p[2 * N_PTS + j];
            xs[j] = xv[s];
            ys[j] = yv[s];
            zs[j] = zv[s];
            dist[s] = 1e10f;
        }
#pragma unroll
        for (int q = 0; q < 4; q++) {
            x2[q] = pk2(xv[2 * q], xv[2 * q + 1]);
            y2[q] = pk2(yv[2 * q], yv[2 * q + 1]);
            z2[q] = pk2(zv[2 * q], zv[2 * q + 1]);
        }
    }
    __syncthreads();

    int far = 0;
    int buf = 0;
    float* out = sampled + (size_t)b * 3 * N_SMP;

    for (int m = 0; m < N_SMP; m++) {
        float cx = xs[far], cy = ys[far], cz = zs[far];
        if (t == 0) {
            out[m]             = cx;
            out[N_SMP + m]     = cy;
            out[2 * N_SMP + m] = cz;
        }
        P2 ncx = pk2(-cx, -cx);
        P2 ncy = pk2(-cy, -cy);
        P2 ncz = pk2(-cz, -cz);

        unsigned bestb = 0u;
        int bidx = t;
#pragma unroll
        for (int q = 0; q < 4; q++) {
            P2 dx = add2(x2[q], ncx);
            P2 dy = add2(y2[q], ncy);
            P2 dz = add2(z2[q], ncz);
            P2 xx = mul2(dx, dx);
            P2 yy = mul2(dy, dy);
            P2 zz = mul2(dz, dz);
            P2 d2 = add2(add2(xx, yy), zz);
            float nlo = fminf(dist[2 * q], d2.lo);
            float nhi = fminf(dist[2 * q + 1], d2.hi);
            dist[2 * q]     = nlo;
            dist[2 * q + 1] = nhi;
            unsigned blo = __float_as_uint(nlo);
            if (blo > bestb) { bestb = blo; bidx = t + (q << 11); }
            unsigned bhi = __float_as_uint(nhi);
            if (bhi > bestb) { bestb = bhi; bidx = t + (q << 11) + 1024; }
        }

        unsigned wmax = __reduce_max_sync(0xffffffffu, bestb);
        unsigned cand = (bestb == wmax) ? (unsigned)bidx : 0xffffffffu;
        unsigned widx = __reduce_min_sync(0xffffffffu, cand);
        if (lane == 0) { s_val[buf][warp] = wmax; s_idx[buf][warp] = widx; }
        __syncthreads();

        unsigned v = s_val[buf][lane];
        unsigned i = s_idx[buf][lane];
        unsigned gmax = __reduce_max_sync(0xffffffffu, v);
        unsigned gc   = (v == gmax) ? i : 0xffffffffu;
        far = (int)__reduce_min_sync(0xffffffffu, gc);
        buf ^= 1;
    }
}

// ---------------------------------------------------------------------------
// Kernel 2: 4-NN + channel max-pool, full-chip version.
// grid (32, 8) x 256 threads. Each block handles 64 queries; each query is
// split across 4 "part" threads that scan interleaved candidates j = 4i+p
// (consecutive float4s per group -> conflict-free LDS). Candidate tile is
// chunked (2 x 4096 pts, 64 KB) so 2 CTAs co-reside per SM. Per-part top-4
// lists are merged lexicographically by (dist, idx) via shfl within the
// 4-lane group, preserving top_k's first-index tie-break. Each part then
// max-pools its own 32 channels.
// ---------------------------------------------------------------------------
#define CHUNK_PTS 4096

__global__ void __launch_bounds__(256, 2)
knn_pool_kernel(const float* __restrict__ feats,
                const float* __restrict__ pos,
                const float* __restrict__ sampled,
                float* __restrict__ pooled)
{
    extern __shared__ float4 tile[];   // [4096] = 64 KB: (x, y, z, p2)

    const int b = blockIdx.y;
    const int t = threadIdx.x;
    const int part = t & 3;
    const int q = blockIdx.x * 64 + (t >> 2);

    const float* sp = sampled + (size_t)b * 3 * N_SMP;
    float sx = sp[q];
    float sy = sp[N_SMP + q];
    float sz = sp[2 * N_SMP + q];
    float s2 = __fadd_rn(__fadd_rn(__fmul_rn(sx, sx), __fmul_rn(sy, sy)),
                         __fmul_rn(sz, sz));

    const float* p = pos + (size_t)b * 3 * N_PTS;

    const float INF = __int_as_float(0x7f800000);
    float d0 = INF, d1 = INF, d2 = INF, d3 = INF;
    int   i0 = 0x7fffffff, i1 = 0x7fffffff, i2 = 0x7fffffff, i3 = 0x7fffffff;

    for (int chunk = 0; chunk < N_PTS / CHUNK_PTS; chunk++) {
        const int base = chunk * CHUNK_PTS;
        __syncthreads();   // previous chunk fully consumed before overwrite
        for (int j = t; j < CHUNK_PTS; j += 256) {
            int g = base + j;
            float px = p[g];
            float py = p[N_PTS + g];
            float pz = p[2 * N_PTS + g];
            float p2 = __fadd_rn(__fadd_rn(__fmul_rn(px, px), __fmul_rn(py, py)),
                                 __fmul_rn(pz, pz));
            tile[j] = make_float4(px, py, pz, p2);
        }
        __syncthreads();

        // part p scans e = 4i+p: ascending global index within a part,
        // so strict '<' insertion keeps first occurrence on exact ties.
#pragma unroll 4
        for (int i = 0; i < CHUNK_PTS / 4; i++) {
            int e = (i << 2) + part;
            float4 pt = tile[e];
            float cross = __fadd_rn(__fadd_rn(__fmul_rn(sx, pt.x), __fmul_rn(sy, pt.y)),
                                    __fmul_rn(sz, pt.z));
            float dv = __fsub_rn(__fadd_rn(s2, pt.w), __fmul_rn(2.0f, cross));
            if (dv < d3) {
                int j = base + e;
                if (dv < d2) {
                    d3 = d2; i3 = i2;
                    if (dv < d1) {
                        d2 = d1; i2 = i1;
                        if (dv < d0) { d1 = d0; i1 = i0; d0 = dv; i0 = j; }
                        else         { d1 = dv; i1 = j; }
                    } else { d2 = dv; i2 = j; }
                } else { d3 = dv; i3 = j; }
            }
        }
    }

    // merge the four per-part sorted top-4 lists: 4 rounds of (d, idx)-min
    // over the 4-lane group (lanes 4q..4q+3 via shfl width=4).
    int mi[4];
#pragma unroll
    for (int r = 0; r < 4; r++) {
        float hd = d0;
        int   hi = i0;
#pragma unroll
        for (int off = 1; off < 4; off <<= 1) {
            float od = __shfl_xor_sync(0xffffffffu, hd, off, 4);
            int   oi = __shfl_xor_sync(0xffffffffu, hi, off, 4);
            if (od < hd || (od == hd && oi < hi)) { hd = od; hi = oi; }
        }
        mi[r] = hi;
        if (hi == i0) {   // global indices unique -> exact pop test
            d0 = d1; i0 = i1;
            d1 = d2; i1 = i2;
            d2 = d3; i2 = i3;
            d3 = INF; i3 = 0x7fffffff;
        }
    }

    // each part max-pools its own 32 channels over the 4 neighbors
    const float* f0 = feats + (size_t)b * CHANNELS * N_PTS;
    float* outp = pooled + (size_t)b * CHANNELS * N_SMP + q;
#pragma unroll 4
    for (int cc = 0; cc < CHANNELS / 4; cc++) {
        int c = part * (CHANNELS / 4) + cc;
        const float* fc = f0 + (size_t)c * N_PTS;
        float v = fmaxf(fmaxf(__ldg(fc + mi[0]), __ldg(fc + mi[1])),
                        fmaxf(__ldg(fc + mi[2]), __ldg(fc + mi[3])));
        outp[(size_t)c * N_SMP] = v;
    }
}

// ---------------------------------------------------------------------------
// Launch
// ---------------------------------------------------------------------------
extern "C" void kernel_launch(void* const* d_in, const int* in_sizes, int n_in,
                              void* d_out, int out_size)
{
    const float* feats = (const float*)d_in[0];   // (8,128,8192)
    const float* pos   = (const float*)d_in[1];   // (8,3,8192)

    float* pooled  = (float*)d_out;                                    // (8,128,2048)
    float* sampled = (float*)d_out + (size_t)BATCH * CHANNELS * N_SMP; // (8,3,2048)

    const int fps_smem = 3 * N_PTS * (int)sizeof(float);        // 96 KB
    const int knn_smem = CHUNK_PTS * (int)sizeof(float4);       // 64 KB
    cudaFuncSetAttribute(fps_kernel,
                         cudaFuncAttributeMaxDynamicSharedMemorySize, fps_smem);
    cudaFuncSetAttribute(knn_pool_kernel,
                         cudaFuncAttributeMaxDynamicSharedMemorySize, knn_smem);

    fps_kernel<<<BATCH, 1024, fps_smem>>>(pos, sampled);

    dim3 grid(N_SMP / 64, BATCH);
    knn_pool_kernel<<<grid, 256, knn_smem>>>(feats, pos, sampled, pooled);
}